// round 15
// baseline (speedup 1.0000x reference)
#include <cuda_runtime.h>
#include <cuda_fp16.h>
#include <cstdint>

// VectorQuantizer on GB300 (sm_103a) — Round 15: fused per-rowTile gather/finalize inside
// the persistent MMA kernel; prep+esq combined into one launch. 2 launches total.
// inputs  : d_in[0] = X [16,1024,256] f32  (N=16384, D=256)
//           d_in[1] = E [8192,256]    f32  (K=8192)
// output  : d_out f32 = [ quantized_sg (N*D) | indices (N) | loss (1) | perplexity (1) ]

#define N_TOK  16384
#define D_DIM  256
#define K_CODE 8192

#define BM 128
#define BN 128
#define HS 264                        // padded row stride in halfs (528B: LDSM conflict-free)
#define TILE_HALFS (128 * HS)
#define TILE_B   (TILE_HALFS * 2)     // 67584 bytes per [128 x 256] fp16 tile
#define MT_STRIDE (16 * HS * 2)       // 8448 bytes per 16 rows

#define OFF_X    0
#define OFF_E    TILE_B               // two E buffers
#define SMEM_BYTES (3 * TILE_B)       // 202752

#define N_CT (K_CODE / BN)            // 64 code tiles
#define N_RT (N_TOK / BM)             // 128 row tiles
#define N_UNITS (N_RT * 8)            // 1024 units (rowTile x octant of 8 code tiles)
#define GRID_MMA 148
#define N_SLOT 32                     // 8 octants x 4 warpCol
#define DELTA 0.02f

__device__ __half g_Xt[N_RT * TILE_HALFS];
__device__ __half g_Et[N_CT * TILE_HALFS];
__device__ float g_esq[K_CODE];
__device__ float g_p1min[N_TOK * N_SLOT];
__device__ int   g_p1idx[N_TOK * N_SLOT];
__device__ float g_p2min[N_TOK * N_SLOT];
__device__ int   g_p2idx[N_TOK * N_SLOT];
__device__ int   g_counts[K_CODE];
__device__ int   g_rtDone[N_RT];
__device__ float g_rtSum[N_RT];
__device__ int   g_rtTilesDone;

// ============================ helpers ============================
__device__ __forceinline__ uint32_t smem_u32(const void* p) {
    uint32_t a;
    asm("{ .reg .u64 t; cvta.to.shared.u64 t, %1; cvt.u32.u64 %0, t; }" : "=r"(a) : "l"(p));
    return a;
}
__device__ __forceinline__ void mma_f16(float* d, uint32_t a0, uint32_t a1, uint32_t a2,
                                        uint32_t a3, uint32_t b0, uint32_t b1) {
    asm volatile(
        "mma.sync.aligned.m16n8k16.row.col.f32.f16.f16.f32 "
        "{%0,%1,%2,%3}, {%4,%5,%6,%7}, {%8,%9}, {%0,%1,%2,%3};"
        : "+f"(d[0]), "+f"(d[1]), "+f"(d[2]), "+f"(d[3])
        : "r"(a0), "r"(a1), "r"(a2), "r"(a3), "r"(b0), "r"(b1));
}
#define LDSM4(r0, r1, r2, r3, addr) \
    asm volatile("ldmatrix.sync.aligned.m8n8.x4.shared.b16 {%0,%1,%2,%3}, [%4];" \
                 : "=r"(r0), "=r"(r1), "=r"(r2), "=r"(r3) : "r"(addr))

#define MBARRIER_INIT(a, c) \
    asm volatile("mbarrier.init.shared.b64 [%0], %1;" :: "r"((uint32_t)(a)), "r"((uint32_t)(c)) : "memory")
#define MBARRIER_EXPECT_TX(a, bytes) \
    asm volatile("mbarrier.arrive.expect_tx.shared.b64 _, [%0], %1;" \
                 :: "r"((uint32_t)(a)), "r"((uint32_t)(bytes)) : "memory")
#define MBARRIER_WAIT_PARITY(a, ph) do {                                              \
    uint32_t _m = (uint32_t)(a); uint32_t _p = (uint32_t)(ph); uint32_t _d;           \
    asm volatile("{\n\t.reg .pred p;\n\t"                                             \
        "mbarrier.try_wait.parity.acquire.cta.shared::cta.b64 p, [%1], %2;\n\t"       \
        "selp.b32 %0, 1, 0, p;\n\t}" : "=r"(_d) : "r"(_m), "r"(_p) : "memory");       \
    if (!_d) {                                                                        \
        asm volatile("{\n\t.reg .pred P1;\n\tWL_%=:\n\t"                              \
            "mbarrier.try_wait.parity.acquire.cta.shared::cta.b64 P1, [%0], %1, 0x989680;\n\t" \
            "@P1 bra.uni WD_%=;\n\tbra.uni WL_%=;\n\tWD_%=:\n\t}"                     \
            :: "r"(_m), "r"(_p) : "memory");                                          \
    }                                                                                 \
} while (0)

__device__ __forceinline__ void bulk_cp(uint32_t dst, const void* src, uint32_t bytes, uint32_t mbar) {
    asm volatile(
        "cp.async.bulk.shared::cluster.global.mbarrier::complete_tx::bytes [%0], [%1], %2, [%3];"
        :: "r"(dst), "l"(src), "r"(bytes), "r"(mbar) : "memory");
}

// pack 8-bit id into low mantissa; key remains an ordinary float (perturbation <= ~1e-3)
__device__ __forceinline__ float packkey(float s, uint32_t id) {
    return __uint_as_float((__float_as_uint(s) & 0xFFFFFF00u) | id);
}

// ============================ prep (fp32->fp16 tiles) + esq + zero, one launch ============================
__global__ void vq_prep_kernel(const float* __restrict__ X, const float* __restrict__ E) {
    if (blockIdx.x < 1024) {
        // --- fp16 tile-padded conversion ---
        const int NX4 = N_TOK * D_DIM / 4;
        const int NT4 = NX4 + K_CODE * D_DIM / 4;
        for (int t = blockIdx.x * blockDim.x + threadIdx.x; t < NT4; t += 1024 * 256) {
            bool isX = t < NX4;
            int  e4  = isX ? t : t - NX4;
            float4 v = isX ? ((const float4*)X)[e4] : ((const float4*)E)[e4];
            half2 p0 = __halves2half2(__float2half_rn(v.x), __float2half_rn(v.y));
            half2 p1 = __halves2half2(__float2half_rn(v.z), __float2half_rn(v.w));
            int row = (e4 * 4) >> 8;
            int d   = (e4 * 4) & 255;
            int rt  = row >> 7;
            int r   = row & 127;
            __half* dst = (isX ? g_Xt : g_Et) + (size_t)rt * TILE_HALFS + r * HS + d;
            *(half2*)(dst)     = p0;
            *(half2*)(dst + 2) = p1;
        }
    } else {
        // --- esq + zero counters ---
        int eb = blockIdx.x - 1024;           // 0..1023
        if (eb == 0) {
            if (threadIdx.x < N_RT) g_rtDone[threadIdx.x] = 0;
            if (threadIdx.x == 0) g_rtTilesDone = 0;
        }
        int gwarp = eb * 8 + (threadIdx.x >> 5);
        int lane  = threadIdx.x & 31;
        const float* row = E + (size_t)gwarp * D_DIM;
        float s = 0.f;
#pragma unroll
        for (int q = 0; q < D_DIM / 32; ++q) {
            float v = row[lane + 32 * q];
            s = fmaf(v, v, s);
        }
#pragma unroll
        for (int o = 16; o; o >>= 1) s += __shfl_xor_sync(0xffffffffu, s, o);
        if (lane == 0) { g_esq[gwarp] = s; g_counts[gwarp] = 0; }
    }
}

// ============================ persistent f16 GEMM + fused gather/finalize ============================
__global__ void __launch_bounds__(512, 1)
vq_mma_kernel(const float* __restrict__ X, const float* __restrict__ E,
              float* __restrict__ outQ, float* __restrict__ outIdx,
              float* __restrict__ outLoss, float* __restrict__ outPerp,
              int writeExtras) {
    extern __shared__ char smem[];
    __shared__ __align__(8) uint64_t s_mbar[3];
    __shared__ int   candList[16][16];
    __shared__ int   candCnt[16];
    __shared__ float warpSsq[16];
    __shared__ float sh[512];
    __shared__ int   s_done, s_fin;

    const int tid  = threadIdx.x;
    const int wid  = tid >> 5;
    const int lane = tid & 31;
    const int quad = lane >> 2;
    const int qt   = lane & 3;
    const int warpRow = wid >> 2;   // 0..3 (32 rows each)
    const int warpCol = wid & 3;    // 0..3 (32 cols each)
    const uint32_t sb = smem_u32(smem);
    const uint32_t mbE0 = smem_u32(&s_mbar[0]);
    const uint32_t mbE1 = smem_u32(&s_mbar[1]);
    const uint32_t mbX  = smem_u32(&s_mbar[2]);

    const int lr = lane & 7;
    const int lb = (lane >> 3) & 1;
    const int lc = lane >> 4;
    const uint32_t aOff = ((uint32_t)(warpRow * 32 + lb * 8 + lr) * HS + (uint32_t)lc * 8) * 2;
    const uint32_t bOff = ((uint32_t)(warpCol * 32 + lc * 8 + lr) * HS + (uint32_t)lb * 8) * 2;

    const int c = blockIdx.x;
    const int uStart = (c * N_UNITS) / GRID_MMA;
    const int uEnd   = ((c + 1) * N_UNITS) / GRID_MMA;
    const int nU = uEnd - uStart;
    const int L  = nU * 8;

    if (tid == 0) {
        MBARRIER_INIT(mbE0, 1);
        MBARRIER_INIT(mbE1, 1);
        MBARRIER_INIT(mbX, 1);
        asm volatile("fence.proxy.async.shared::cta;" ::: "memory");
    }
    __syncthreads();

    auto etileOf = [&](int q) {
        int u = uStart + (q >> 3);
        return ((u & 7) << 3) + (q & 7);
    };

    if (tid == 0) {
        MBARRIER_EXPECT_TX(mbX, TILE_B);
        bulk_cp(sb + OFF_X, (const char*)g_Xt + (size_t)(uStart >> 3) * TILE_B, TILE_B, mbX);
        MBARRIER_EXPECT_TX(mbE0, TILE_B);
        bulk_cp(sb + OFF_E, (const char*)g_Et + (size_t)etileOf(0) * TILE_B, TILE_B, mbE0);
    }

    float m1[4], m2[4];
#pragma unroll
    for (int j = 0; j < 4; ++j) { m1[j] = 3.3e38f; m2[j] = 3.3e38f; }

    int prevRow = uStart >> 3;
    int xWait = 0;
    int p = 0;

#pragma unroll 1
    for (int ui = 0; ui < nU; ++ui) {
        const int u = uStart + ui;
        const int rowTile = u >> 3;
        const int oct = u & 7;
        const int rowBase = rowTile * BM;
        bool newRow = (ui == 0) || (rowTile != prevRow);
        prevRow = rowTile;

        if (ui > 0 && newRow) {
            __syncthreads();
            if (tid == 0) {
                MBARRIER_EXPECT_TX(mbX, TILE_B);
                bulk_cp(sb + OFF_X, (const char*)g_Xt + (size_t)rowTile * TILE_B, TILE_B, mbX);
            }
        }

#pragma unroll 1
        for (int tl = 0; tl < 8; ++tl, ++p) {
            __syncthreads();
            if (tid == 0 && p + 1 < L) {
                uint32_t mb = ((p + 1) & 1) ? mbE1 : mbE0;
                MBARRIER_EXPECT_TX(mb, TILE_B);
                bulk_cp(sb + OFF_E + (uint32_t)((p + 1) & 1) * TILE_B,
                        (const char*)g_Et + (size_t)etileOf(p + 1) * TILE_B, TILE_B, mb);
            }
            MBARRIER_WAIT_PARITY((p & 1) ? mbE1 : mbE0, (p >> 1) & 1);
            if (tl == 0 && newRow) { MBARRIER_WAIT_PARITY(mbX, xWait & 1); xWait++; }

            const uint32_t eBase = sb + OFF_E + (uint32_t)(p & 1) * TILE_B;
            const uint32_t xBase = sb + OFF_X;

            float d[2][4][4];
#pragma unroll
            for (int mt = 0; mt < 2; ++mt)
#pragma unroll
                for (int nt = 0; nt < 4; ++nt)
#pragma unroll
                    for (int r = 0; r < 4; ++r) d[mt][nt][r] = 0.f;

#pragma unroll
            for (int kk = 0; kk < 16; ++kk) {
                const uint32_t kByte = (uint32_t)kk * 32;
                uint32_t bh[8];
                LDSM4(bh[0], bh[1], bh[2], bh[3], eBase + bOff + kByte);
                LDSM4(bh[4], bh[5], bh[6], bh[7], eBase + bOff + MT_STRIDE + kByte);
#pragma unroll
                for (int mt = 0; mt < 2; ++mt) {
                    uint32_t ah[4];
                    LDSM4(ah[0], ah[1], ah[2], ah[3],
                          xBase + aOff + (uint32_t)mt * MT_STRIDE + kByte);
#pragma unroll
                    for (int nt = 0; nt < 4; ++nt)
                        mma_f16(d[mt][nt], ah[0], ah[1], ah[2], ah[3], bh[nt*2], bh[nt*2+1]);
                }
            }

            // ---- branchless epilogue: 8-bit id = (tl<<5)|(nt<<3)|(qt<<1)|lsb ----
            const int tileBase = (oct * 8 + tl) * BN;
#pragma unroll
            for (int mt = 0; mt < 2; ++mt) {
                const int j0 = mt * 2, j1 = mt * 2 + 1;
#pragma unroll
                for (int nt = 0; nt < 4; ++nt) {
                    int col = tileBase + warpCol * 32 + nt * 8 + 2 * qt;
                    float2 eq = *(const float2*)(g_esq + col);
                    uint32_t id0 = ((uint32_t)tl << 5) | ((uint32_t)nt << 3) | ((uint32_t)qt << 1);
                    float k00 = packkey(fmaf(-2.f, d[mt][nt][0], eq.x), id0);
                    float k01 = packkey(fmaf(-2.f, d[mt][nt][1], eq.y), id0 + 1);
                    float k10 = packkey(fmaf(-2.f, d[mt][nt][2], eq.x), id0);
                    float k11 = packkey(fmaf(-2.f, d[mt][nt][3], eq.y), id0 + 1);
                    float kp0 = fminf(k00, k01);
                    float kp1 = fminf(k10, k11);
                    float t0 = fmaxf(kp0, m1[j0]); m1[j0] = fminf(kp0, m1[j0]); m2[j0] = fminf(t0, m2[j0]);
                    float t1 = fmaxf(kp1, m1[j1]); m1[j1] = fminf(kp1, m1[j1]); m2[j1] = fminf(t1, m2[j1]);
                }
            }
        }

        // ---- unit flush: quad-merge best-2, write slot = oct*4 + warpCol ----
#pragma unroll
        for (int j = 0; j < 4; ++j) {
#pragma unroll
            for (int o = 1; o <= 2; o <<= 1) {
                float o1 = __shfl_xor_sync(0xffffffffu, m1[j], o);
                float o2 = __shfl_xor_sync(0xffffffffu, m2[j], o);
                float hi = fmaxf(m1[j], o1);
                m1[j] = fminf(m1[j], o1);
                m2[j] = fminf(fminf(m2[j], o2), hi);
            }
        }
        if (qt == 0) {
            int slot = oct * 4 + warpCol;
#pragma unroll
            for (int mt = 0; mt < 2; ++mt) {
#pragma unroll
                for (int h = 0; h < 2; ++h) {
                    int j   = mt * 2 + h;
                    int row = rowBase + warpRow * 32 + mt * 16 + h * 8 + quad;
                    size_t o = (size_t)row * N_SLOT + slot;
                    uint32_t b1 = __float_as_uint(m1[j]) & 0xFFu;
                    uint32_t b2 = __float_as_uint(m2[j]) & 0xFFu;
                    int c1 = (oct * 8 + (int)(b1 >> 5)) * BN + warpCol * 32
                           + (int)((b1 >> 3) & 3) * 8 + (int)((b1 >> 1) & 3) * 2 + (int)(b1 & 1);
                    int c2 = (oct * 8 + (int)(b2 >> 5)) * BN + warpCol * 32
                           + (int)((b2 >> 3) & 3) * 8 + (int)((b2 >> 1) & 3) * 2 + (int)(b2 & 1);
                    g_p1min[o] = m1[j]; g_p1idx[o] = c1;
                    g_p2min[o] = m2[j]; g_p2idx[o] = c2;
                }
            }
        }
#pragma unroll
        for (int j = 0; j < 4; ++j) { m1[j] = 3.3e38f; m2[j] = 3.3e38f; }

        // ---- rowTile completion tick ----
        __threadfence();
        __syncthreads();
        if (tid == 0) s_done = atomicAdd(&g_rtDone[rowTile], 1);
        __syncthreads();

        if (s_done == 7) {
            // this CTA completes rowTile: fused gather + refine for its 128 rows
            __threadfence();   // acquire side
            float ssqWarp = 0.f;
#pragma unroll 1
            for (int rIt = 0; rIt < 8; ++rIt) {
                int row = rowBase + rIt * 16 + wid;
                if (lane == 0) candCnt[wid] = 0;
                __syncwarp();
                size_t pb = (size_t)row * N_SLOT;
                float v0 = __ldcg(&g_p1min[pb + lane]);
                int   x0 = __ldcg(&g_p1idx[pb + lane]);
                float v1 = __ldcg(&g_p2min[pb + lane]);
                int   x1 = __ldcg(&g_p2idx[pb + lane]);
                float mn = fminf(v0, v1);
#pragma unroll
                for (int o = 16; o; o >>= 1) mn = fminf(mn, __shfl_xor_sync(0xffffffffu, mn, o));
                float thr = mn + DELTA;
                if (v0 <= thr) { int pI = atomicAdd(&candCnt[wid], 1); if (pI < 16) candList[wid][pI] = x0; }
                if (v1 <= thr) { int pI = atomicAdd(&candCnt[wid], 1); if (pI < 16) candList[wid][pI] = x1; }
                __syncwarp();
                int cnt = candCnt[wid];
                if (cnt > 16) cnt = 16;

                const float4* x4 = (const float4*)(X + (size_t)row * D_DIM);
                float4 xv0 = x4[lane], xv1 = x4[lane + 32];

                float bsc = 3.4e38f;
                int   bidx = 0x7fffffff;
                for (int jj = 0; jj < cnt; ++jj) {
                    int cc = candList[wid][jj];
                    const float4* ec = (const float4*)(E + (size_t)cc * D_DIM);
                    float4 e0 = ec[lane], e1 = ec[lane + 32];
                    float dt = xv0.x * e0.x;
                    dt = fmaf(xv0.y, e0.y, dt);
                    dt = fmaf(xv0.z, e0.z, dt);
                    dt = fmaf(xv0.w, e0.w, dt);
                    dt = fmaf(xv1.x, e1.x, dt);
                    dt = fmaf(xv1.y, e1.y, dt);
                    dt = fmaf(xv1.z, e1.z, dt);
                    dt = fmaf(xv1.w, e1.w, dt);
#pragma unroll
                    for (int o = 16; o; o >>= 1) dt += __shfl_xor_sync(0xffffffffu, dt, o);
                    float sc = __ldg(&g_esq[cc]) - 2.f * dt;
                    if (sc < bsc || (sc == bsc && cc < bidx)) { bsc = sc; bidx = cc; }
                }
                int idx = bidx;

                const float4* e4 = (const float4*)(E + (size_t)idx * D_DIM);
                float4* o4 = (float4*)(outQ + (size_t)row * D_DIM);
                float s = 0.f;
                {
                    float4 e = e4[lane];
                    float dx = e.x - xv0.x, dy = e.y - xv0.y, dz = e.z - xv0.z, dw = e.w - xv0.w;
                    float4 o; o.x = xv0.x + dx; o.y = xv0.y + dy; o.z = xv0.z + dz; o.w = xv0.w + dw;
                    o4[lane] = o;
                    s += dx * dx + dy * dy + dz * dz + dw * dw;
                }
                {
                    float4 e = e4[lane + 32];
                    float dx = e.x - xv1.x, dy = e.y - xv1.y, dz = e.z - xv1.z, dw = e.w - xv1.w;
                    float4 o; o.x = xv1.x + dx; o.y = xv1.y + dy; o.z = xv1.z + dz; o.w = xv1.w + dw;
                    o4[lane + 32] = o;
                    s += dx * dx + dy * dy + dz * dz + dw * dw;
                }
#pragma unroll
                for (int o = 16; o; o >>= 1) s += __shfl_xor_sync(0xffffffffu, s, o);
                ssqWarp += s;
                if (lane == 0) {
                    atomicAdd(&g_counts[idx], 1);
                    if (writeExtras) outIdx[row] = (float)idx;
                }
            }

            if (lane == 0) warpSsq[wid] = ssqWarp;
            __threadfence();   // order this thread's outQ/count writes
            __syncthreads();
            if (tid == 0) {
                float bs = 0.f;
#pragma unroll
                for (int w = 0; w < 16; ++w) bs += warpSsq[w];
                g_rtSum[rowTile] = bs;
                __threadfence();
                int td = atomicAdd(&g_rtTilesDone, 1);
                s_fin = (td == N_RT - 1) ? 1 : 0;
            }
            __syncthreads();

            if (s_fin) {
                __threadfence();   // acquire: all rowTiles' sums + counts visible
                // loss
                float ls = (tid < N_RT) ? __ldcg(&g_rtSum[tid]) : 0.f;
                sh[tid] = ls;
                __syncthreads();
                for (int o = 256; o; o >>= 1) {
                    if (tid < o) sh[tid] += sh[tid + o];
                    __syncthreads();
                }
                float sumsq = sh[0];
                __syncthreads();
                // perplexity
                const float invN = 1.f / (float)N_TOK;
                float ent = 0.f;
                for (int k = tid; k < K_CODE; k += 512) {
                    int cc = __ldcg(&g_counts[k]);
                    if (cc > 0) {
                        float pp = (float)cc * invN;
                        ent += pp * logf(pp + 1e-10f);
                    }
                }
                sh[tid] = ent;
                __syncthreads();
                for (int o = 256; o; o >>= 1) {
                    if (tid < o) sh[tid] += sh[tid + o];
                    __syncthreads();
                }
                if (tid == 0 && writeExtras) {
                    outLoss[0] = 0.25f * sumsq / (float)(N_TOK * D_DIM);
                    outPerp[0] = expf(-sh[0]);
                }
            }
        }
    }
}

// ============================ launcher ============================
extern "C" void kernel_launch(void* const* d_in, const int* in_sizes, int n_in,
                              void* d_out, int out_size) {
    const float* X = (const float*)d_in[0];
    const float* E = (const float*)d_in[1];
    float* out = (float*)d_out;

    float* outQ    = out;
    float* outIdx  = out + (size_t)N_TOK * D_DIM;
    float* outLoss = outIdx + N_TOK;
    float* outPerp = outLoss + 1;
    int writeExtras = (out_size >= N_TOK * D_DIM + N_TOK + 2) ? 1 : 0;

    cudaFuncSetAttribute(vq_mma_kernel,
                         cudaFuncAttributeMaxDynamicSharedMemorySize, SMEM_BYTES);

    vq_prep_kernel<<<2048, 256>>>(X, E);   // blocks 0-1023: fp16 tiles; 1024-2047: esq+zero
    vq_mma_kernel<<<GRID_MMA, 512, SMEM_BYTES>>>(X, E, outQ, outIdx, outLoss, outPerp, writeExtras);
}

// round 16
// speedup vs baseline: 1.0621x; 1.0621x over previous
#include <cuda_runtime.h>
#include <cuda_fp16.h>
#include <cstdint>

// VectorQuantizer on GB300 (sm_103a) — Round 16: revert fused gather (R14 structure),
// merged prep+esq launch, register-double-buffered B fragments in the kk loop.
// inputs  : d_in[0] = X [16,1024,256] f32  (N=16384, D=256)
//           d_in[1] = E [8192,256]    f32  (K=8192)
// output  : d_out f32 = [ quantized_sg (N*D) | indices (N) | loss (1) | perplexity (1) ]

#define N_TOK  16384
#define D_DIM  256
#define K_CODE 8192

#define BM 128
#define BN 128
#define HS 264                        // padded row stride in halfs (528B: LDSM conflict-free)
#define TILE_HALFS (128 * HS)
#define TILE_B   (TILE_HALFS * 2)     // 67584 bytes per [128 x 256] fp16 tile
#define MT_STRIDE (16 * HS * 2)       // 8448 bytes per 16 rows

#define OFF_X    0
#define OFF_E    TILE_B               // two E buffers
#define SMEM_BYTES (3 * TILE_B)       // 202752

#define N_CT (K_CODE / BN)            // 64 code tiles
#define N_RT (N_TOK / BM)             // 128 row tiles
#define N_UNITS (N_RT * 8)            // 1024 units (rowTile x octant of 8 code tiles)
#define GRID_MMA 148
#define N_SLOT 32                     // 8 octants x 4 warpCol
#define GATHER_BLOCKS (N_TOK / 8)     // 2048
#define DELTA 0.02f

__device__ __half g_Xt[N_RT * TILE_HALFS];
__device__ __half g_Et[N_CT * TILE_HALFS];
__device__ float g_esq[K_CODE];
__device__ float g_p1min[N_TOK * N_SLOT];
__device__ int   g_p1idx[N_TOK * N_SLOT];
__device__ float g_p2min[N_TOK * N_SLOT];
__device__ int   g_p2idx[N_TOK * N_SLOT];
__device__ int   g_counts[K_CODE];
__device__ float g_blocksum[GATHER_BLOCKS];
__device__ int   g_done;

// ============================ helpers ============================
__device__ __forceinline__ uint32_t smem_u32(const void* p) {
    uint32_t a;
    asm("{ .reg .u64 t; cvta.to.shared.u64 t, %1; cvt.u32.u64 %0, t; }" : "=r"(a) : "l"(p));
    return a;
}
__device__ __forceinline__ void mma_f16(float* d, uint32_t a0, uint32_t a1, uint32_t a2,
                                        uint32_t a3, uint32_t b0, uint32_t b1) {
    asm volatile(
        "mma.sync.aligned.m16n8k16.row.col.f32.f16.f16.f32 "
        "{%0,%1,%2,%3}, {%4,%5,%6,%7}, {%8,%9}, {%0,%1,%2,%3};"
        : "+f"(d[0]), "+f"(d[1]), "+f"(d[2]), "+f"(d[3])
        : "r"(a0), "r"(a1), "r"(a2), "r"(a3), "r"(b0), "r"(b1));
}
#define LDSM4(r0, r1, r2, r3, addr) \
    asm volatile("ldmatrix.sync.aligned.m8n8.x4.shared.b16 {%0,%1,%2,%3}, [%4];" \
                 : "=r"(r0), "=r"(r1), "=r"(r2), "=r"(r3) : "r"(addr))

#define MBARRIER_INIT(a, c) \
    asm volatile("mbarrier.init.shared.b64 [%0], %1;" :: "r"((uint32_t)(a)), "r"((uint32_t)(c)) : "memory")
#define MBARRIER_EXPECT_TX(a, bytes) \
    asm volatile("mbarrier.arrive.expect_tx.shared.b64 _, [%0], %1;" \
                 :: "r"((uint32_t)(a)), "r"((uint32_t)(bytes)) : "memory")
#define MBARRIER_WAIT_PARITY(a, ph) do {                                              \
    uint32_t _m = (uint32_t)(a); uint32_t _p = (uint32_t)(ph); uint32_t _d;           \
    asm volatile("{\n\t.reg .pred p;\n\t"                                             \
        "mbarrier.try_wait.parity.acquire.cta.shared::cta.b64 p, [%1], %2;\n\t"       \
        "selp.b32 %0, 1, 0, p;\n\t}" : "=r"(_d) : "r"(_m), "r"(_p) : "memory");       \
    if (!_d) {                                                                        \
        asm volatile("{\n\t.reg .pred P1;\n\tWL_%=:\n\t"                              \
            "mbarrier.try_wait.parity.acquire.cta.shared::cta.b64 P1, [%0], %1, 0x989680;\n\t" \
            "@P1 bra.uni WD_%=;\n\tbra.uni WL_%=;\n\tWD_%=:\n\t}"                     \
            :: "r"(_m), "r"(_p) : "memory");                                          \
    }                                                                                 \
} while (0)

__device__ __forceinline__ void bulk_cp(uint32_t dst, const void* src, uint32_t bytes, uint32_t mbar) {
    asm volatile(
        "cp.async.bulk.shared::cluster.global.mbarrier::complete_tx::bytes [%0], [%1], %2, [%3];"
        :: "r"(dst), "l"(src), "r"(bytes), "r"(mbar) : "memory");
}

// pack 8-bit id into low mantissa; key remains an ordinary float (perturbation <= ~1e-3)
__device__ __forceinline__ float packkey(float s, uint32_t id) {
    return __uint_as_float((__float_as_uint(s) & 0xFFFFFF00u) | id);
}

// ============================ prep (fp32->fp16 tiles) + esq + zero, one launch ============================
__global__ void vq_prep_kernel(const float* __restrict__ X, const float* __restrict__ E) {
    if (blockIdx.x < 1024) {
        const int NX4 = N_TOK * D_DIM / 4;
        const int NT4 = NX4 + K_CODE * D_DIM / 4;
        for (int t = blockIdx.x * blockDim.x + threadIdx.x; t < NT4; t += 1024 * 256) {
            bool isX = t < NX4;
            int  e4  = isX ? t : t - NX4;
            float4 v = isX ? ((const float4*)X)[e4] : ((const float4*)E)[e4];
            half2 p0 = __halves2half2(__float2half_rn(v.x), __float2half_rn(v.y));
            half2 p1 = __halves2half2(__float2half_rn(v.z), __float2half_rn(v.w));
            int row = (e4 * 4) >> 8;
            int d   = (e4 * 4) & 255;
            int rt  = row >> 7;
            int r   = row & 127;
            __half* dst = (isX ? g_Xt : g_Et) + (size_t)rt * TILE_HALFS + r * HS + d;
            *(half2*)(dst)     = p0;
            *(half2*)(dst + 2) = p1;
        }
    } else {
        int eb = blockIdx.x - 1024;           // 0..1023
        if (eb == 0 && threadIdx.x == 0) g_done = 0;
        int gwarp = eb * 8 + (threadIdx.x >> 5);
        int lane  = threadIdx.x & 31;
        const float* row = E + (size_t)gwarp * D_DIM;
        float s = 0.f;
#pragma unroll
        for (int q = 0; q < D_DIM / 32; ++q) {
            float v = row[lane + 32 * q];
            s = fmaf(v, v, s);
        }
#pragma unroll
        for (int o = 16; o; o >>= 1) s += __shfl_xor_sync(0xffffffffu, s, o);
        if (lane == 0) { g_esq[gwarp] = s; g_counts[gwarp] = 0; }
    }
}

// ============================ persistent f16 approx GEMM ============================
__global__ void __launch_bounds__(512, 1)
vq_mma_kernel() {
    extern __shared__ char smem[];
    __shared__ __align__(8) uint64_t s_mbar[3];   // [0],[1]: E bufs; [2]: X

    const int tid  = threadIdx.x;
    const int wid  = tid >> 5;
    const int lane = tid & 31;
    const int quad = lane >> 2;
    const int qt   = lane & 3;
    const int warpRow = wid >> 2;   // 0..3 (32 rows each)
    const int warpCol = wid & 3;    // 0..3 (32 cols each)
    const uint32_t sb = smem_u32(smem);
    const uint32_t mbE0 = smem_u32(&s_mbar[0]);
    const uint32_t mbE1 = smem_u32(&s_mbar[1]);
    const uint32_t mbX  = smem_u32(&s_mbar[2]);

    // LDSM per-lane base offsets (bytes)
    const int lr = lane & 7;
    const int lb = (lane >> 3) & 1;
    const int lc = lane >> 4;
    const uint32_t aOff = ((uint32_t)(warpRow * 32 + lb * 8 + lr) * HS + (uint32_t)lc * 8) * 2;
    const uint32_t bOff = ((uint32_t)(warpCol * 32 + lc * 8 + lr) * HS + (uint32_t)lb * 8) * 2;

    // contiguous unit range for this CTA
    const int c = blockIdx.x;
    const int uStart = (c * N_UNITS) / GRID_MMA;
    const int uEnd   = ((c + 1) * N_UNITS) / GRID_MMA;
    const int nU = uEnd - uStart;
    const int L  = nU * 8;             // E-tile stream length

    if (tid == 0) {
        MBARRIER_INIT(mbE0, 1);
        MBARRIER_INIT(mbE1, 1);
        MBARRIER_INIT(mbX, 1);
        asm volatile("fence.proxy.async.shared::cta;" ::: "memory");
    }
    __syncthreads();

    auto etileOf = [&](int q) {
        int u = uStart + (q >> 3);
        return ((u & 7) << 3) + (q & 7);
    };

    if (tid == 0) {
        MBARRIER_EXPECT_TX(mbX, TILE_B);
        bulk_cp(sb + OFF_X, (const char*)g_Xt + (size_t)(uStart >> 3) * TILE_B, TILE_B, mbX);
        MBARRIER_EXPECT_TX(mbE0, TILE_B);
        bulk_cp(sb + OFF_E, (const char*)g_Et + (size_t)etileOf(0) * TILE_B, TILE_B, mbE0);
    }

    float m1[4], m2[4];
#pragma unroll
    for (int j = 0; j < 4; ++j) { m1[j] = 3.3e38f; m2[j] = 3.3e38f; }

    int prevRow = uStart >> 3;
    int xWait = 0;
    int p = 0;

#pragma unroll 1
    for (int ui = 0; ui < nU; ++ui) {
        const int u = uStart + ui;
        const int rowTile = u >> 3;
        const int oct = u & 7;
        const int rowBase = rowTile * BM;
        bool newRow = (ui == 0) || (rowTile != prevRow);
        prevRow = rowTile;

        if (ui > 0 && newRow) {
            __syncthreads();          // all warps done reading old X
            if (tid == 0) {
                MBARRIER_EXPECT_TX(mbX, TILE_B);
                bulk_cp(sb + OFF_X, (const char*)g_Xt + (size_t)rowTile * TILE_B, TILE_B, mbX);
            }
        }

#pragma unroll 1
        for (int tl = 0; tl < 8; ++tl, ++p) {
            __syncthreads();          // frees buffer (p+1)&1 (read at p-1)
            if (tid == 0 && p + 1 < L) {
                uint32_t mb = ((p + 1) & 1) ? mbE1 : mbE0;
                MBARRIER_EXPECT_TX(mb, TILE_B);
                bulk_cp(sb + OFF_E + (uint32_t)((p + 1) & 1) * TILE_B,
                        (const char*)g_Et + (size_t)etileOf(p + 1) * TILE_B, TILE_B, mb);
            }
            MBARRIER_WAIT_PARITY((p & 1) ? mbE1 : mbE0, (p >> 1) & 1);
            if (tl == 0 && newRow) { MBARRIER_WAIT_PARITY(mbX, xWait & 1); xWait++; }

            const uint32_t eBase = sb + OFF_E + (uint32_t)(p & 1) * TILE_B;
            const uint32_t xBase = sb + OFF_X;

            float d[2][4][4];
#pragma unroll
            for (int mt = 0; mt < 2; ++mt)
#pragma unroll
                for (int nt = 0; nt < 4; ++nt)
#pragma unroll
                    for (int r = 0; r < 4; ++r) d[mt][nt][r] = 0.f;

            // ---- kk loop with register-double-buffered B fragments ----
            uint32_t bh[2][8];
            LDSM4(bh[0][0], bh[0][1], bh[0][2], bh[0][3], eBase + bOff);
            LDSM4(bh[0][4], bh[0][5], bh[0][6], bh[0][7], eBase + bOff + MT_STRIDE);
#pragma unroll
            for (int kk = 0; kk < 16; ++kk) {
                const int cur = kk & 1;
                if (kk < 15) {
                    const uint32_t nb = (uint32_t)(kk + 1) * 32;
                    LDSM4(bh[cur ^ 1][0], bh[cur ^ 1][1], bh[cur ^ 1][2], bh[cur ^ 1][3],
                          eBase + bOff + nb);
                    LDSM4(bh[cur ^ 1][4], bh[cur ^ 1][5], bh[cur ^ 1][6], bh[cur ^ 1][7],
                          eBase + bOff + MT_STRIDE + nb);
                }
                const uint32_t kByte = (uint32_t)kk * 32;
#pragma unroll
                for (int mt = 0; mt < 2; ++mt) {
                    uint32_t ah[4];
                    LDSM4(ah[0], ah[1], ah[2], ah[3],
                          xBase + aOff + (uint32_t)mt * MT_STRIDE + kByte);
#pragma unroll
                    for (int nt = 0; nt < 4; ++nt)
                        mma_f16(d[mt][nt], ah[0], ah[1], ah[2], ah[3],
                                bh[cur][nt*2], bh[cur][nt*2+1]);
                }
            }

            // ---- branchless epilogue: 8-bit id = (tl<<5)|(nt<<3)|(qt<<1)|lsb ----
            const int tileBase = (oct * 8 + tl) * BN;
#pragma unroll
            for (int mt = 0; mt < 2; ++mt) {
                const int j0 = mt * 2, j1 = mt * 2 + 1;
#pragma unroll
                for (int nt = 0; nt < 4; ++nt) {
                    int col = tileBase + warpCol * 32 + nt * 8 + 2 * qt;
                    float2 eq = *(const float2*)(g_esq + col);
                    uint32_t id0 = ((uint32_t)tl << 5) | ((uint32_t)nt << 3) | ((uint32_t)qt << 1);
                    float k00 = packkey(fmaf(-2.f, d[mt][nt][0], eq.x), id0);
                    float k01 = packkey(fmaf(-2.f, d[mt][nt][1], eq.y), id0 + 1);
                    float k10 = packkey(fmaf(-2.f, d[mt][nt][2], eq.x), id0);
                    float k11 = packkey(fmaf(-2.f, d[mt][nt][3], eq.y), id0 + 1);
                    float kp0 = fminf(k00, k01);
                    float kp1 = fminf(k10, k11);
                    float t0 = fmaxf(kp0, m1[j0]); m1[j0] = fminf(kp0, m1[j0]); m2[j0] = fminf(t0, m2[j0]);
                    float t1 = fmaxf(kp1, m1[j1]); m1[j1] = fminf(kp1, m1[j1]); m2[j1] = fminf(t1, m2[j1]);
                }
            }
        }

        // ---- unit flush: quad-merge best-2 across qt, write slot = oct*4 + warpCol ----
#pragma unroll
        for (int j = 0; j < 4; ++j) {
#pragma unroll
            for (int o = 1; o <= 2; o <<= 1) {
                float o1 = __shfl_xor_sync(0xffffffffu, m1[j], o);
                float o2 = __shfl_xor_sync(0xffffffffu, m2[j], o);
                float hi = fmaxf(m1[j], o1);
                m1[j] = fminf(m1[j], o1);
                m2[j] = fminf(fminf(m2[j], o2), hi);
            }
        }
        if (qt == 0) {
            int slot = oct * 4 + warpCol;
#pragma unroll
            for (int mt = 0; mt < 2; ++mt) {
#pragma unroll
                for (int h = 0; h < 2; ++h) {
                    int j   = mt * 2 + h;
                    int row = rowBase + warpRow * 32 + mt * 16 + h * 8 + quad;
                    size_t o = (size_t)row * N_SLOT + slot;
                    uint32_t b1 = __float_as_uint(m1[j]) & 0xFFu;
                    uint32_t b2 = __float_as_uint(m2[j]) & 0xFFu;
                    int c1 = (oct * 8 + (int)(b1 >> 5)) * BN + warpCol * 32
                           + (int)((b1 >> 3) & 3) * 8 + (int)((b1 >> 1) & 3) * 2 + (int)(b1 & 1);
                    int c2 = (oct * 8 + (int)(b2 >> 5)) * BN + warpCol * 32
                           + (int)((b2 >> 3) & 3) * 8 + (int)((b2 >> 1) & 3) * 2 + (int)(b2 & 1);
                    g_p1min[o] = m1[j]; g_p1idx[o] = c1;
                    g_p2min[o] = m2[j]; g_p2idx[o] = c2;
                }
            }
        }
#pragma unroll
        for (int j = 0; j < 4; ++j) { m1[j] = 3.3e38f; m2[j] = 3.3e38f; }
    }
}

// ============================ gather + refine + (last block) finalize ============================
__global__ void vq_gather_kernel(const float* __restrict__ X, const float* __restrict__ E,
                                 float* __restrict__ outQ, float* __restrict__ outIdx,
                                 float* __restrict__ outLoss, float* __restrict__ outPerp,
                                 int writeExtras) {
    __shared__ float warpSums[8];
    __shared__ int   candList[8][16];
    __shared__ int   candCnt[8];
    __shared__ int   isLast;
    int lwarp = threadIdx.x >> 5;
    int lane  = threadIdx.x & 31;
    int row   = blockIdx.x * 8 + lwarp;

    if (lane == 0) candCnt[lwarp] = 0;
    __syncwarp();

    size_t pb = (size_t)row * N_SLOT;
    float v0 = g_p1min[pb + lane];
    int   x0 = g_p1idx[pb + lane];
    float v1 = g_p2min[pb + lane];
    int   x1 = g_p2idx[pb + lane];
    float mn = fminf(v0, v1);
#pragma unroll
    for (int o = 16; o; o >>= 1) mn = fminf(mn, __shfl_xor_sync(0xffffffffu, mn, o));
    float thr = mn + DELTA;
    if (v0 <= thr) { int p = atomicAdd(&candCnt[lwarp], 1); if (p < 16) candList[lwarp][p] = x0; }
    if (v1 <= thr) { int p = atomicAdd(&candCnt[lwarp], 1); if (p < 16) candList[lwarp][p] = x1; }
    __syncwarp();
    int cnt = candCnt[lwarp];
    if (cnt > 16) cnt = 16;

    const float4* x4 = (const float4*)(X + (size_t)row * D_DIM);
    float4 xv0 = x4[lane], xv1 = x4[lane + 32];

    float bsc = 3.4e38f;
    int   bidx = 0x7fffffff;
    for (int j = 0; j < cnt; ++j) {
        int cc = candList[lwarp][j];
        const float4* ec = (const float4*)(E + (size_t)cc * D_DIM);
        float4 e0 = ec[lane], e1 = ec[lane + 32];
        float dt = xv0.x * e0.x;
        dt = fmaf(xv0.y, e0.y, dt);
        dt = fmaf(xv0.z, e0.z, dt);
        dt = fmaf(xv0.w, e0.w, dt);
        dt = fmaf(xv1.x, e1.x, dt);
        dt = fmaf(xv1.y, e1.y, dt);
        dt = fmaf(xv1.z, e1.z, dt);
        dt = fmaf(xv1.w, e1.w, dt);
#pragma unroll
        for (int o = 16; o; o >>= 1) dt += __shfl_xor_sync(0xffffffffu, dt, o);
        float sc = __ldg(&g_esq[cc]) - 2.f * dt;
        if (sc < bsc || (sc == bsc && cc < bidx)) { bsc = sc; bidx = cc; }
    }
    int idx = bidx;

    const float4* e4 = (const float4*)(E + (size_t)idx * D_DIM);
    float4* o4 = (float4*)(outQ + (size_t)row * D_DIM);

    float s = 0.f;
    {
        float4 e = e4[lane];
        float dx = e.x - xv0.x, dy = e.y - xv0.y, dz = e.z - xv0.z, dw = e.w - xv0.w;
        float4 o; o.x = xv0.x + dx; o.y = xv0.y + dy; o.z = xv0.z + dz; o.w = xv0.w + dw;
        o4[lane] = o;
        s += dx * dx + dy * dy + dz * dz + dw * dw;
    }
    {
        float4 e = e4[lane + 32];
        float dx = e.x - xv1.x, dy = e.y - xv1.y, dz = e.z - xv1.z, dw = e.w - xv1.w;
        float4 o; o.x = xv1.x + dx; o.y = xv1.y + dy; o.z = xv1.z + dz; o.w = xv1.w + dw;
        o4[lane + 32] = o;
        s += dx * dx + dy * dy + dz * dz + dw * dw;
    }
#pragma unroll
    for (int o = 16; o; o >>= 1) s += __shfl_xor_sync(0xffffffffu, s, o);
    if (lane == 0) {
        warpSums[lwarp] = s;
        atomicAdd(&g_counts[idx], 1);
        if (writeExtras) outIdx[row] = (float)idx;
    }
    __syncthreads();
    if (threadIdx.x == 0) {
        float bs = 0.f;
#pragma unroll
        for (int w = 0; w < 8; ++w) bs += warpSums[w];
        g_blocksum[blockIdx.x] = bs;
        __threadfence();
        int t = atomicAdd(&g_done, 1);
        isLast = (t == GATHER_BLOCKS - 1) ? 1 : 0;
    }
    __syncthreads();

    if (isLast) {
        __shared__ float sh[256];
        int tid = threadIdx.x;
        float ss = 0.f;
        for (int b = tid; b < GATHER_BLOCKS; b += 256) ss += g_blocksum[b];
        sh[tid] = ss;
        __syncthreads();
        for (int o = 128; o; o >>= 1) {
            if (tid < o) sh[tid] += sh[tid + o];
            __syncthreads();
        }
        float sumsq = sh[0];
        __syncthreads();

        const float invN = 1.f / (float)N_TOK;
        float ent = 0.f;
        for (int k = tid; k < K_CODE; k += 256) {
            int cc = g_counts[k];
            if (cc > 0) {
                float pp = (float)cc * invN;
                ent += pp * logf(pp + 1e-10f);
            }
        }
        sh[tid] = ent;
        __syncthreads();
        for (int o = 128; o; o >>= 1) {
            if (tid < o) sh[tid] += sh[tid + o];
            __syncthreads();
        }
        if (tid == 0 && writeExtras) {
            outLoss[0] = 0.25f * sumsq / (float)(N_TOK * D_DIM);
            outPerp[0] = expf(-sh[0]);
        }
    }
}

// ============================ launcher ============================
extern "C" void kernel_launch(void* const* d_in, const int* in_sizes, int n_in,
                              void* d_out, int out_size) {
    const float* X = (const float*)d_in[0];
    const float* E = (const float*)d_in[1];
    float* out = (float*)d_out;

    float* outQ    = out;
    float* outIdx  = out + (size_t)N_TOK * D_DIM;
    float* outLoss = outIdx + N_TOK;
    float* outPerp = outLoss + 1;
    int writeExtras = (out_size >= N_TOK * D_DIM + N_TOK + 2) ? 1 : 0;

    cudaFuncSetAttribute(vq_mma_kernel,
                         cudaFuncAttributeMaxDynamicSharedMemorySize, SMEM_BYTES);

    vq_prep_kernel<<<2048, 256>>>(X, E);   // blocks 0-1023: fp16 tiles; 1024-2047: esq+zero
    vq_mma_kernel<<<GRID_MMA, 512, SMEM_BYTES>>>();   // 148 persistent CTAs, 1024 units
    vq_gather_kernel<<<GATHER_BLOCKS, 256>>>(X, E, outQ, outIdx, outLoss, outPerp, writeExtras);
}

// round 17
// speedup vs baseline: 1.0697x; 1.0072x over previous
#include <cuda_runtime.h>
#include <cuda_fp16.h>
#include <cstdint>

// VectorQuantizer on GB300 (sm_103a) — Round 17: fp16-accumulator HMMA (2x rate theory)
// Everything else identical to R16 (best passing: 206.8us).
// inputs  : d_in[0] = X [16,1024,256] f32  (N=16384, D=256)
//           d_in[1] = E [8192,256]    f32  (K=8192)
// output  : d_out f32 = [ quantized_sg (N*D) | indices (N) | loss (1) | perplexity (1) ]

#define N_TOK  16384
#define D_DIM  256
#define K_CODE 8192

#define BM 128
#define BN 128
#define HS 264                        // padded row stride in halfs (528B: LDSM conflict-free)
#define TILE_HALFS (128 * HS)
#define TILE_B   (TILE_HALFS * 2)     // 67584 bytes per [128 x 256] fp16 tile
#define MT_STRIDE (16 * HS * 2)       // 8448 bytes per 16 rows

#define OFF_X    0
#define OFF_E    TILE_B               // two E buffers
#define SMEM_BYTES (3 * TILE_B)       // 202752

#define N_CT (K_CODE / BN)            // 64 code tiles
#define N_RT (N_TOK / BM)             // 128 row tiles
#define N_UNITS (N_RT * 8)            // 1024 units (rowTile x octant of 8 code tiles)
#define GRID_MMA 148
#define N_SLOT 32                     // 8 octants x 4 warpCol
#define GATHER_BLOCKS (N_TOK / 8)     // 2048
#define DELTA 0.15f                   // covers fp16-accumulation error (worst ~0.06)

__device__ __half g_Xt[N_RT * TILE_HALFS];
__device__ __half g_Et[N_CT * TILE_HALFS];
__device__ float g_esq[K_CODE];
__device__ float g_p1min[N_TOK * N_SLOT];
__device__ int   g_p1idx[N_TOK * N_SLOT];
__device__ float g_p2min[N_TOK * N_SLOT];
__device__ int   g_p2idx[N_TOK * N_SLOT];
__device__ int   g_counts[K_CODE];
__device__ float g_blocksum[GATHER_BLOCKS];
__device__ int   g_done;

// ============================ helpers ============================
__device__ __forceinline__ uint32_t smem_u32(const void* p) {
    uint32_t a;
    asm("{ .reg .u64 t; cvta.to.shared.u64 t, %1; cvt.u32.u64 %0, t; }" : "=r"(a) : "l"(p));
    return a;
}
// fp16-accumulator HMMA: D(f16) = A(f16)*B(f16) + D(f16); 2 output regs
__device__ __forceinline__ void mma_f16h(uint32_t* d, uint32_t a0, uint32_t a1, uint32_t a2,
                                         uint32_t a3, uint32_t b0, uint32_t b1) {
    asm volatile(
        "mma.sync.aligned.m16n8k16.row.col.f16.f16.f16.f16 "
        "{%0,%1}, {%2,%3,%4,%5}, {%6,%7}, {%0,%1};"
        : "+r"(d[0]), "+r"(d[1])
        : "r"(a0), "r"(a1), "r"(a2), "r"(a3), "r"(b0), "r"(b1));
}
#define LDSM4(r0, r1, r2, r3, addr) \
    asm volatile("ldmatrix.sync.aligned.m8n8.x4.shared.b16 {%0,%1,%2,%3}, [%4];" \
                 : "=r"(r0), "=r"(r1), "=r"(r2), "=r"(r3) : "r"(addr))

#define MBARRIER_INIT(a, c) \
    asm volatile("mbarrier.init.shared.b64 [%0], %1;" :: "r"((uint32_t)(a)), "r"((uint32_t)(c)) : "memory")
#define MBARRIER_EXPECT_TX(a, bytes) \
    asm volatile("mbarrier.arrive.expect_tx.shared.b64 _, [%0], %1;" \
                 :: "r"((uint32_t)(a)), "r"((uint32_t)(bytes)) : "memory")
#define MBARRIER_WAIT_PARITY(a, ph) do {                                              \
    uint32_t _m = (uint32_t)(a); uint32_t _p = (uint32_t)(ph); uint32_t _d;           \
    asm volatile("{\n\t.reg .pred p;\n\t"                                             \
        "mbarrier.try_wait.parity.acquire.cta.shared::cta.b64 p, [%1], %2;\n\t"       \
        "selp.b32 %0, 1, 0, p;\n\t}" : "=r"(_d) : "r"(_m), "r"(_p) : "memory");       \
    if (!_d) {                                                                        \
        asm volatile("{\n\t.reg .pred P1;\n\tWL_%=:\n\t"                              \
            "mbarrier.try_wait.parity.acquire.cta.shared::cta.b64 P1, [%0], %1, 0x989680;\n\t" \
            "@P1 bra.uni WD_%=;\n\tbra.uni WL_%=;\n\tWD_%=:\n\t}"                     \
            :: "r"(_m), "r"(_p) : "memory");                                          \
    }                                                                                 \
} while (0)

__device__ __forceinline__ void bulk_cp(uint32_t dst, const void* src, uint32_t bytes, uint32_t mbar) {
    asm volatile(
        "cp.async.bulk.shared::cluster.global.mbarrier::complete_tx::bytes [%0], [%1], %2, [%3];"
        :: "r"(dst), "l"(src), "r"(bytes), "r"(mbar) : "memory");
}

// pack 8-bit id into low mantissa; key remains an ordinary float (perturbation <= ~1e-3)
__device__ __forceinline__ float packkey(float s, uint32_t id) {
    return __uint_as_float((__float_as_uint(s) & 0xFFFFFF00u) | id);
}

// ============================ prep (fp32->fp16 tiles) + esq + zero, one launch ============================
__global__ void vq_prep_kernel(const float* __restrict__ X, const float* __restrict__ E) {
    if (blockIdx.x < 1024) {
        const int NX4 = N_TOK * D_DIM / 4;
        const int NT4 = NX4 + K_CODE * D_DIM / 4;
        for (int t = blockIdx.x * blockDim.x + threadIdx.x; t < NT4; t += 1024 * 256) {
            bool isX = t < NX4;
            int  e4  = isX ? t : t - NX4;
            float4 v = isX ? ((const float4*)X)[e4] : ((const float4*)E)[e4];
            half2 p0 = __halves2half2(__float2half_rn(v.x), __float2half_rn(v.y));
            half2 p1 = __halves2half2(__float2half_rn(v.z), __float2half_rn(v.w));
            int row = (e4 * 4) >> 8;
            int d   = (e4 * 4) & 255;
            int rt  = row >> 7;
            int r   = row & 127;
            __half* dst = (isX ? g_Xt : g_Et) + (size_t)rt * TILE_HALFS + r * HS + d;
            *(half2*)(dst)     = p0;
            *(half2*)(dst + 2) = p1;
        }
    } else {
        int eb = blockIdx.x - 1024;           // 0..1023
        if (eb == 0 && threadIdx.x == 0) g_done = 0;
        int gwarp = eb * 8 + (threadIdx.x >> 5);
        int lane  = threadIdx.x & 31;
        const float* row = E + (size_t)gwarp * D_DIM;
        float s = 0.f;
#pragma unroll
        for (int q = 0; q < D_DIM / 32; ++q) {
            float v = row[lane + 32 * q];
            s = fmaf(v, v, s);
        }
#pragma unroll
        for (int o = 16; o; o >>= 1) s += __shfl_xor_sync(0xffffffffu, s, o);
        if (lane == 0) { g_esq[gwarp] = s; g_counts[gwarp] = 0; }
    }
}

// ============================ persistent f16 approx GEMM (fp16 accumulators) ============================
__global__ void __launch_bounds__(512, 1)
vq_mma_kernel() {
    extern __shared__ char smem[];
    __shared__ __align__(8) uint64_t s_mbar[3];   // [0],[1]: E bufs; [2]: X

    const int tid  = threadIdx.x;
    const int wid  = tid >> 5;
    const int lane = tid & 31;
    const int quad = lane >> 2;
    const int qt   = lane & 3;
    const int warpRow = wid >> 2;   // 0..3 (32 rows each)
    const int warpCol = wid & 3;    // 0..3 (32 cols each)
    const uint32_t sb = smem_u32(smem);
    const uint32_t mbE0 = smem_u32(&s_mbar[0]);
    const uint32_t mbE1 = smem_u32(&s_mbar[1]);
    const uint32_t mbX  = smem_u32(&s_mbar[2]);

    // LDSM per-lane base offsets (bytes)
    const int lr = lane & 7;
    const int lb = (lane >> 3) & 1;
    const int lc = lane >> 4;
    const uint32_t aOff = ((uint32_t)(warpRow * 32 + lb * 8 + lr) * HS + (uint32_t)lc * 8) * 2;
    const uint32_t bOff = ((uint32_t)(warpCol * 32 + lc * 8 + lr) * HS + (uint32_t)lb * 8) * 2;

    // contiguous unit range for this CTA
    const int c = blockIdx.x;
    const int uStart = (c * N_UNITS) / GRID_MMA;
    const int uEnd   = ((c + 1) * N_UNITS) / GRID_MMA;
    const int nU = uEnd - uStart;
    const int L  = nU * 8;             // E-tile stream length

    if (tid == 0) {
        MBARRIER_INIT(mbE0, 1);
        MBARRIER_INIT(mbE1, 1);
        MBARRIER_INIT(mbX, 1);
        asm volatile("fence.proxy.async.shared::cta;" ::: "memory");
    }
    __syncthreads();

    auto etileOf = [&](int q) {
        int u = uStart + (q >> 3);
        return ((u & 7) << 3) + (q & 7);
    };

    if (tid == 0) {
        MBARRIER_EXPECT_TX(mbX, TILE_B);
        bulk_cp(sb + OFF_X, (const char*)g_Xt + (size_t)(uStart >> 3) * TILE_B, TILE_B, mbX);
        MBARRIER_EXPECT_TX(mbE0, TILE_B);
        bulk_cp(sb + OFF_E, (const char*)g_Et + (size_t)etileOf(0) * TILE_B, TILE_B, mbE0);
    }

    float m1[4], m2[4];
#pragma unroll
    for (int j = 0; j < 4; ++j) { m1[j] = 3.3e38f; m2[j] = 3.3e38f; }

    int prevRow = uStart >> 3;
    int xWait = 0;
    int p = 0;

#pragma unroll 1
    for (int ui = 0; ui < nU; ++ui) {
        const int u = uStart + ui;
        const int rowTile = u >> 3;
        const int oct = u & 7;
        const int rowBase = rowTile * BM;
        bool newRow = (ui == 0) || (rowTile != prevRow);
        prevRow = rowTile;

        if (ui > 0 && newRow) {
            __syncthreads();          // all warps done reading old X
            if (tid == 0) {
                MBARRIER_EXPECT_TX(mbX, TILE_B);
                bulk_cp(sb + OFF_X, (const char*)g_Xt + (size_t)rowTile * TILE_B, TILE_B, mbX);
            }
        }

#pragma unroll 1
        for (int tl = 0; tl < 8; ++tl, ++p) {
            __syncthreads();          // frees buffer (p+1)&1 (read at p-1)
            if (tid == 0 && p + 1 < L) {
                uint32_t mb = ((p + 1) & 1) ? mbE1 : mbE0;
                MBARRIER_EXPECT_TX(mb, TILE_B);
                bulk_cp(sb + OFF_E + (uint32_t)((p + 1) & 1) * TILE_B,
                        (const char*)g_Et + (size_t)etileOf(p + 1) * TILE_B, TILE_B, mb);
            }
            MBARRIER_WAIT_PARITY((p & 1) ? mbE1 : mbE0, (p >> 1) & 1);
            if (tl == 0 && newRow) { MBARRIER_WAIT_PARITY(mbX, xWait & 1); xWait++; }

            const uint32_t eBase = sb + OFF_E + (uint32_t)(p & 1) * TILE_B;
            const uint32_t xBase = sb + OFF_X;

            uint32_t d[2][4][2];    // fp16 accumulators: half2 pairs
#pragma unroll
            for (int mt = 0; mt < 2; ++mt)
#pragma unroll
                for (int nt = 0; nt < 4; ++nt) { d[mt][nt][0] = 0u; d[mt][nt][1] = 0u; }

            // ---- kk loop with register-double-buffered B fragments ----
            uint32_t bh[2][8];
            LDSM4(bh[0][0], bh[0][1], bh[0][2], bh[0][3], eBase + bOff);
            LDSM4(bh[0][4], bh[0][5], bh[0][6], bh[0][7], eBase + bOff + MT_STRIDE);
#pragma unroll
            for (int kk = 0; kk < 16; ++kk) {
                const int cur = kk & 1;
                if (kk < 15) {
                    const uint32_t nb = (uint32_t)(kk + 1) * 32;
                    LDSM4(bh[cur ^ 1][0], bh[cur ^ 1][1], bh[cur ^ 1][2], bh[cur ^ 1][3],
                          eBase + bOff + nb);
                    LDSM4(bh[cur ^ 1][4], bh[cur ^ 1][5], bh[cur ^ 1][6], bh[cur ^ 1][7],
                          eBase + bOff + MT_STRIDE + nb);
                }
                const uint32_t kByte = (uint32_t)kk * 32;
#pragma unroll
                for (int mt = 0; mt < 2; ++mt) {
                    uint32_t ah[4];
                    LDSM4(ah[0], ah[1], ah[2], ah[3],
                          xBase + aOff + (uint32_t)mt * MT_STRIDE + kByte);
#pragma unroll
                    for (int nt = 0; nt < 4; ++nt)
                        mma_f16h(d[mt][nt], ah[0], ah[1], ah[2], ah[3],
                                 bh[cur][nt*2], bh[cur][nt*2+1]);
                }
            }

            // ---- branchless epilogue: 8-bit id = (tl<<5)|(nt<<3)|(qt<<1)|lsb ----
            const int tileBase = (oct * 8 + tl) * BN;
#pragma unroll
            for (int mt = 0; mt < 2; ++mt) {
                const int j0 = mt * 2, j1 = mt * 2 + 1;
#pragma unroll
                for (int nt = 0; nt < 4; ++nt) {
                    int col = tileBase + warpCol * 32 + nt * 8 + 2 * qt;
                    float2 eq = *(const float2*)(g_esq + col);
                    float2 f0 = __half22float2(*(half2*)&d[mt][nt][0]);  // rows h=0
                    float2 f1 = __half22float2(*(half2*)&d[mt][nt][1]);  // rows h=1
                    uint32_t id0 = ((uint32_t)tl << 5) | ((uint32_t)nt << 3) | ((uint32_t)qt << 1);
                    float k00 = packkey(fmaf(-2.f, f0.x, eq.x), id0);
                    float k01 = packkey(fmaf(-2.f, f0.y, eq.y), id0 + 1);
                    float k10 = packkey(fmaf(-2.f, f1.x, eq.x), id0);
                    float k11 = packkey(fmaf(-2.f, f1.y, eq.y), id0 + 1);
                    float kp0 = fminf(k00, k01);
                    float kp1 = fminf(k10, k11);
                    float t0 = fmaxf(kp0, m1[j0]); m1[j0] = fminf(kp0, m1[j0]); m2[j0] = fminf(t0, m2[j0]);
                    float t1 = fmaxf(kp1, m1[j1]); m1[j1] = fminf(kp1, m1[j1]); m2[j1] = fminf(t1, m2[j1]);
                }
            }
        }

        // ---- unit flush: quad-merge best-2 across qt, write slot = oct*4 + warpCol ----
#pragma unroll
        for (int j = 0; j < 4; ++j) {
#pragma unroll
            for (int o = 1; o <= 2; o <<= 1) {
                float o1 = __shfl_xor_sync(0xffffffffu, m1[j], o);
                float o2 = __shfl_xor_sync(0xffffffffu, m2[j], o);
                float hi = fmaxf(m1[j], o1);
                m1[j] = fminf(m1[j], o1);
                m2[j] = fminf(fminf(m2[j], o2), hi);
            }
        }
        if (qt == 0) {
            int slot = oct * 4 + warpCol;
#pragma unroll
            for (int mt = 0; mt < 2; ++mt) {
#pragma unroll
                for (int h = 0; h < 2; ++h) {
                    int j   = mt * 2 + h;
                    int row = rowBase + warpRow * 32 + mt * 16 + h * 8 + quad;
                    size_t o = (size_t)row * N_SLOT + slot;
                    uint32_t b1 = __float_as_uint(m1[j]) & 0xFFu;
                    uint32_t b2 = __float_as_uint(m2[j]) & 0xFFu;
                    int c1 = (oct * 8 + (int)(b1 >> 5)) * BN + warpCol * 32
                           + (int)((b1 >> 3) & 3) * 8 + (int)((b1 >> 1) & 3) * 2 + (int)(b1 & 1);
                    int c2 = (oct * 8 + (int)(b2 >> 5)) * BN + warpCol * 32
                           + (int)((b2 >> 3) & 3) * 8 + (int)((b2 >> 1) & 3) * 2 + (int)(b2 & 1);
                    g_p1min[o] = m1[j]; g_p1idx[o] = c1;
                    g_p2min[o] = m2[j]; g_p2idx[o] = c2;
                }
            }
        }
#pragma unroll
        for (int j = 0; j < 4; ++j) { m1[j] = 3.3e38f; m2[j] = 3.3e38f; }
    }
}

// ============================ gather + refine + (last block) finalize ============================
__global__ void vq_gather_kernel(const float* __restrict__ X, const float* __restrict__ E,
                                 float* __restrict__ outQ, float* __restrict__ outIdx,
                                 float* __restrict__ outLoss, float* __restrict__ outPerp,
                                 int writeExtras) {
    __shared__ float warpSums[8];
    __shared__ int   candList[8][16];
    __shared__ int   candCnt[8];
    __shared__ int   isLast;
    int lwarp = threadIdx.x >> 5;
    int lane  = threadIdx.x & 31;
    int row   = blockIdx.x * 8 + lwarp;

    if (lane == 0) candCnt[lwarp] = 0;
    __syncwarp();

    size_t pb = (size_t)row * N_SLOT;
    float v0 = g_p1min[pb + lane];
    int   x0 = g_p1idx[pb + lane];
    float v1 = g_p2min[pb + lane];
    int   x1 = g_p2idx[pb + lane];
    float mn = fminf(v0, v1);
#pragma unroll
    for (int o = 16; o; o >>= 1) mn = fminf(mn, __shfl_xor_sync(0xffffffffu, mn, o));
    float thr = mn + DELTA;
    if (v0 <= thr) { int p = atomicAdd(&candCnt[lwarp], 1); if (p < 16) candList[lwarp][p] = x0; }
    if (v1 <= thr) { int p = atomicAdd(&candCnt[lwarp], 1); if (p < 16) candList[lwarp][p] = x1; }
    __syncwarp();
    int cnt = candCnt[lwarp];
    if (cnt > 16) cnt = 16;

    const float4* x4 = (const float4*)(X + (size_t)row * D_DIM);
    float4 xv0 = x4[lane], xv1 = x4[lane + 32];

    float bsc = 3.4e38f;
    int   bidx = 0x7fffffff;
    for (int j = 0; j < cnt; ++j) {
        int cc = candList[lwarp][j];
        const float4* ec = (const float4*)(E + (size_t)cc * D_DIM);
        float4 e0 = ec[lane], e1 = ec[lane + 32];
        float dt = xv0.x * e0.x;
        dt = fmaf(xv0.y, e0.y, dt);
        dt = fmaf(xv0.z, e0.z, dt);
        dt = fmaf(xv0.w, e0.w, dt);
        dt = fmaf(xv1.x, e1.x, dt);
        dt = fmaf(xv1.y, e1.y, dt);
        dt = fmaf(xv1.z, e1.z, dt);
        dt = fmaf(xv1.w, e1.w, dt);
#pragma unroll
        for (int o = 16; o; o >>= 1) dt += __shfl_xor_sync(0xffffffffu, dt, o);
        float sc = __ldg(&g_esq[cc]) - 2.f * dt;
        if (sc < bsc || (sc == bsc && cc < bidx)) { bsc = sc; bidx = cc; }
    }
    int idx = bidx;

    const float4* e4 = (const float4*)(E + (size_t)idx * D_DIM);
    float4* o4 = (float4*)(outQ + (size_t)row * D_DIM);

    float s = 0.f;
    {
        float4 e = e4[lane];
        float dx = e.x - xv0.x, dy = e.y - xv0.y, dz = e.z - xv0.z, dw = e.w - xv0.w;
        float4 o; o.x = xv0.x + dx; o.y = xv0.y + dy; o.z = xv0.z + dz; o.w = xv0.w + dw;
        o4[lane] = o;
        s += dx * dx + dy * dy + dz * dz + dw * dw;
    }
    {
        float4 e = e4[lane + 32];
        float dx = e.x - xv1.x, dy = e.y - xv1.y, dz = e.z - xv1.z, dw = e.w - xv1.w;
        float4 o; o.x = xv1.x + dx; o.y = xv1.y + dy; o.z = xv1.z + dz; o.w = xv1.w + dw;
        o4[lane + 32] = o;
        s += dx * dx + dy * dy + dz * dz + dw * dw;
    }
#pragma unroll
    for (int o = 16; o; o >>= 1) s += __shfl_xor_sync(0xffffffffu, s, o);
    if (lane == 0) {
        warpSums[lwarp] = s;
        atomicAdd(&g_counts[idx], 1);
        if (writeExtras) outIdx[row] = (float)idx;
    }
    __syncthreads();
    if (threadIdx.x == 0) {
        float bs = 0.f;
#pragma unroll
        for (int w = 0; w < 8; ++w) bs += warpSums[w];
        g_blocksum[blockIdx.x] = bs;
        __threadfence();
        int t = atomicAdd(&g_done, 1);
        isLast = (t == GATHER_BLOCKS - 1) ? 1 : 0;
    }
    __syncthreads();

    if (isLast) {
        __shared__ float sh[256];
        int tid = threadIdx.x;
        float ss = 0.f;
        for (int b = tid; b < GATHER_BLOCKS; b += 256) ss += g_blocksum[b];
        sh[tid] = ss;
        __syncthreads();
        for (int o = 128; o; o >>= 1) {
            if (tid < o) sh[tid] += sh[tid + o];
            __syncthreads();
        }
        float sumsq = sh[0];
        __syncthreads();

        const float invN = 1.f / (float)N_TOK;
        float ent = 0.f;
        for (int k = tid; k < K_CODE; k += 256) {
            int cc = g_counts[k];
            if (cc > 0) {
                float pp = (float)cc * invN;
                ent += pp * logf(pp + 1e-10f);
            }
        }
        sh[tid] = ent;
        __syncthreads();
        for (int o = 128; o; o >>= 1) {
            if (tid < o) sh[tid] += sh[tid + o];
            __syncthreads();
        }
        if (tid == 0 && writeExtras) {
            outLoss[0] = 0.25f * sumsq / (float)(N_TOK * D_DIM);
            outPerp[0] = expf(-sh[0]);
        }
    }
}

// ============================ launcher ============================
extern "C" void kernel_launch(void* const* d_in, const int* in_sizes, int n_in,
                              void* d_out, int out_size) {
    const float* X = (const float*)d_in[0];
    const float* E = (const float*)d_in[1];
    float* out = (float*)d_out;

    float* outQ    = out;
    float* outIdx  = out + (size_t)N_TOK * D_DIM;
    float* outLoss = outIdx + N_TOK;
    float* outPerp = outLoss + 1;
    int writeExtras = (out_size >= N_TOK * D_DIM + N_TOK + 2) ? 1 : 0;

    cudaFuncSetAttribute(vq_mma_kernel,
                         cudaFuncAttributeMaxDynamicSharedMemorySize, SMEM_BYTES);

    vq_prep_kernel<<<2048, 256>>>(X, E);   // blocks 0-1023: fp16 tiles; 1024-2047: esq+zero
    vq_mma_kernel<<<GRID_MMA, 512, SMEM_BYTES>>>();   // 148 persistent CTAs, 1024 units
    vq_gather_kernel<<<GATHER_BLOCKS, 256>>>(X, E, outQ, outIdx, outLoss, outPerp, writeExtras);
}